// round 14
// baseline (speedup 1.0000x reference)
#include <cuda_runtime.h>
#include <cuda_fp16.h>
#include <math.h>
#include <stdint.h>

#define NTOK   2048
#define SLEN   1024
#define EDIM   1024
#define E4DIM  4096
#define NB     4

// ---------------------------------------------------------------------------
// Scratch
// ---------------------------------------------------------------------------
__device__ float  g_h   [NTOK * EDIM];
__device__ float  g_modsall[5 * 2 * 6144];
__device__ float  g_lamv[NB];
__device__ float  g_part[5 * 64 * 2 * 6144];
__device__ __half g_th  [NTOK * EDIM];
__device__ __half g_hidh[NTOK * E4DIM];
__device__ __half g_xh  [NTOK * 64];
__device__ __half g_qkvh[NTOK * 3 * EDIM];
__device__ __half g_a1h [NTOK * EDIM];
__device__ __half g_a2h [NTOK * EDIM];

// fp16 weights, NATURAL [K][N] layout
__device__ __half g_w_l2e1[64 * EDIM];
__device__ __half g_w_l2e2[EDIM * EDIM];
__device__ __half g_w_qkv [NB * EDIM * 3 * EDIM];
__device__ __half g_w_out [NB * EDIM * EDIM];
__device__ __half g_w_ff1 [NB * EDIM * E4DIM];
__device__ __half g_w_ff2 [NB * E4DIM * EDIM];
__device__ __half g_w_fin [EDIM * 64];

// ---------------------------------------------------------------------------
// Helpers
// ---------------------------------------------------------------------------
__device__ __forceinline__ float warp_sum(float v) {
#pragma unroll
    for (int o = 16; o; o >>= 1) v += __shfl_xor_sync(0xffffffffu, v, o);
    return v;
}

__device__ __forceinline__ void mma_f16(
    float* c, const uint32_t* a, const uint32_t* b)
{
    asm volatile(
        "mma.sync.aligned.m16n8k16.row.col.f32.f16.f16.f32 "
        "{%0,%1,%2,%3}, {%4,%5,%6,%7}, {%8,%9}, {%0,%1,%2,%3};"
        : "+f"(c[0]), "+f"(c[1]), "+f"(c[2]), "+f"(c[3])
        : "r"(a[0]), "r"(a[1]), "r"(a[2]), "r"(a[3]),
          "r"(b[0]), "r"(b[1]));
}

__device__ __forceinline__ void ldsm_x4(uint32_t* r, uint32_t addr) {
    asm volatile("ldmatrix.sync.aligned.m8n8.x4.shared.b16 {%0,%1,%2,%3}, [%4];"
        : "=r"(r[0]), "=r"(r[1]), "=r"(r[2]), "=r"(r[3]) : "r"(addr));
}
__device__ __forceinline__ void ldsm_x4_t(uint32_t* r, uint32_t addr) {
    asm volatile("ldmatrix.sync.aligned.m8n8.x4.trans.shared.b16 {%0,%1,%2,%3}, [%4];"
        : "=r"(r[0]), "=r"(r[1]), "=r"(r[2]), "=r"(r[3]) : "r"(addr));
}

__device__ __forceinline__ void cp_async16(void* smem, const void* gmem) {
    uint32_t s = (uint32_t)__cvta_generic_to_shared(smem);
    asm volatile("cp.async.cg.shared.global [%0], [%1], 16;"
                 :: "r"(s), "l"(gmem));
}
__device__ __forceinline__ void cp_async16_pred(void* smem, const void* gmem, bool p) {
    uint32_t s = (uint32_t)__cvta_generic_to_shared(smem);
    int sz = p ? 16 : 0;
    asm volatile("cp.async.cg.shared.global [%0], [%1], 16, %2;"
                 :: "r"(s), "l"(gmem), "r"(sz));
}
#define CP_COMMIT() asm volatile("cp.async.commit_group;" ::: "memory")
#define CP_WAIT1()  asm volatile("cp.async.wait_group 1;" ::: "memory")

// ---------------------------------------------------------------------------
// Batched fp32 -> fp16 convert over 8 segments (one launch)
// ---------------------------------------------------------------------------
struct CvtSegs {
    const float4* in[8];
    uint2*        out[8];
    int           n4[8];
};

__global__ void __launch_bounds__(256) cvt_all_kernel(CvtSegs segs, int total4)
{
    int i = blockIdx.x * 256 + threadIdx.x;
    if (i >= total4) return;
    int seg = 0, off = i;
#pragma unroll
    for (int s = 0; s < 8; s++) {
        if (off >= segs.n4[s]) { off -= segs.n4[s]; seg++; }
        else break;
    }
    float4 v = __ldg(segs.in[seg] + off);
    uint2 u;
    *reinterpret_cast<__half2*>(&u.x) = __floats2half2_rn(v.x, v.y);
    *reinterpret_cast<__half2*>(&u.y) = __floats2half2_rn(v.z, v.w);
    segs.out[seg][off] = u;
}

// ---------------------------------------------------------------------------
// FP16 tensor-core GEMM (mma.m16n8k16, ldmatrix A non-trans, B trans).
// BK=64, 2-stage cp.async. See R12/R13.
// ---------------------------------------------------------------------------
#define HG_ASZ   (128 * 72)
#define HG_BSZ   (64 * 136)
#define HG_SMEM  ((2 * HG_ASZ + 2 * HG_BSZ) * 2)

template <int MODE>
__global__ void __launch_bounds__(256) hgemm_kernel(
    const __half* __restrict__ A, const __half* __restrict__ W,
    const float* __restrict__ bias, void* __restrict__ Cv,
    int M, int N, int K,
    const float* __restrict__ p1, const float* __restrict__ p2, int goff)
{
    extern __shared__ __half hsm[];
    __half* As = hsm;
    __half* Bs = hsm + 2 * HG_ASZ;

    const int bm  = blockIdx.y * 128;
    const int bn  = blockIdx.x * 128;
    const int tid = threadIdx.x;
    const int wid = tid >> 5, lane = tid & 31;
    const int g = lane >> 2, t = lane & 3;
    const int wm = (wid >> 2) * 64;
    const int wn = (wid & 3) * 32;

    const int KT = K >> 6;

    const int a_row = lane & 15;
    const int a_col = (lane >> 4) << 3;
    const int b_kr  = lane & 15;
    const int b_nc  = (lane >> 4) << 3;

    const uint32_t as_u = (uint32_t)__cvta_generic_to_shared(As);
    const uint32_t bs_u = (uint32_t)__cvta_generic_to_shared(Bs);

    auto load_stage = [&](int s, int k0) {
        __half* as = As + s * HG_ASZ;
        __half* bs = Bs + s * HG_BSZ;
#pragma unroll
        for (int u = 0; u < 4; u++) {
            int l = tid + u * 256;
            int r = l >> 3, c = (l & 7) * 8;
            cp_async16(as + r * 72 + c, A + (size_t)(bm + r) * K + k0 + c);
        }
#pragma unroll
        for (int u = 0; u < 4; u++) {
            int l = tid + u * 256;
            int r = l >> 4, c = (l & 15) * 8;
            bool ok = (bn + c) < N;
            cp_async16_pred(bs + r * 136 + c,
                            W + (size_t)(k0 + r) * N + (ok ? (bn + c) : 0), ok);
        }
    };

    float acc[4][4][4];
#pragma unroll
    for (int mt = 0; mt < 4; mt++)
#pragma unroll
        for (int nt = 0; nt < 4; nt++)
#pragma unroll
            for (int r = 0; r < 4; r++) acc[mt][nt][r] = 0.f;

    load_stage(0, 0);
    CP_COMMIT();

    for (int ki = 0; ki < KT; ki++) {
        if (ki + 1 < KT) load_stage((ki + 1) & 1, (ki + 1) * 64);
        CP_COMMIT();
        CP_WAIT1();
        __syncthreads();

        const uint32_t asb = as_u + (ki & 1) * HG_ASZ * 2;
        const uint32_t bsb = bs_u + (ki & 1) * HG_BSZ * 2;
#pragma unroll
        for (int ks = 0; ks < 64; ks += 16) {
            uint32_t a[4][4], bq[2][4];
#pragma unroll
            for (int mt = 0; mt < 4; mt++)
                ldsm_x4(a[mt], asb + 2 * ((wm + mt * 16 + a_row) * 72 + a_col + ks));
#pragma unroll
            for (int n2 = 0; n2 < 2; n2++)
                ldsm_x4_t(bq[n2], bsb + 2 * ((ks + b_kr) * 136 + wn + n2 * 16 + b_nc));
#pragma unroll
            for (int n2 = 0; n2 < 2; n2++)
#pragma unroll
                for (int hh = 0; hh < 2; hh++) {
                    uint32_t bb[2] = { bq[n2][2 * hh], bq[n2][2 * hh + 1] };
#pragma unroll
                    for (int mt = 0; mt < 4; mt++)
                        mma_f16(acc[mt][n2 * 2 + hh], a[mt], bb);
                }
        }
        __syncthreads();
    }

    float*  Cf = (float*)Cv;
    __half* Ch = (__half*)Cv;
#pragma unroll
    for (int mt = 0; mt < 4; mt++) {
        int r0 = bm + wm + mt * 16 + g;
#pragma unroll
        for (int nt = 0; nt < 4; nt++) {
            int c0 = bn + wn + nt * 8 + 2 * t;
            if (c0 < N) {
#pragma unroll
                for (int half_ = 0; half_ < 2; half_++) {
                    int rr = r0 + half_ * 8;
#pragma unroll
                    for (int e = 0; e < 2; e++) {
                        int cc = c0 + e;
                        float v = acc[mt][nt][half_ * 2 + e];
                        if (bias) v += bias[cc];
                        if (MODE == 1) {
                            float sn = __sinf(p1[cc] * v);
                            v += sn * sn / (p2[cc] + 1e-9f);
                            Ch[(size_t)rr * N + cc] = __float2half(v);
                        } else if (MODE == 2) {
                            int bb = rr >> 10;
                            float gg = p1[bb * 6144 + goff + cc];
                            float sg = 1.f / (1.f + __expf(gg - 1.f));
                            Cf[(size_t)rr * N + cc] += v * sg;
                        } else if (MODE == 3) {
                            Ch[(size_t)rr * N + cc] = __float2half(v);
                        } else {
                            Cf[(size_t)rr * N + cc] = v;
                        }
                    }
                }
            }
        }
    }
}

// ---------------------------------------------------------------------------
// Batched small-M GEMM (M=2): 5 segments, 64-way K split
// ---------------------------------------------------------------------------
__global__ void __launch_bounds__(128) gemm2_part_all(
    const float* __restrict__ emb,
    const float* __restrict__ ada_w, const float* __restrict__ adaf_w,
    float* __restrict__ part)
{
    int z = blockIdx.z;
    int N = (z < 4) ? 6144 : 2048;
    if (blockIdx.x * 512 >= N) return;
    const float* W = (z < 4) ? (ada_w + (size_t)z * EDIM * 6144) : adaf_w;
    float* pseg = part + (size_t)z * 64 * 2 * 6144;

    int n4 = N >> 2;
    int c4 = blockIdx.x * 128 + threadIdx.x;
    int kb = blockIdx.y, k0 = kb * 16;
    float4 s0 = make_float4(0.f, 0.f, 0.f, 0.f);
    float4 s1 = make_float4(0.f, 0.f, 0.f, 0.f);
    const float4* wp = (const float4*)W + (size_t)k0 * n4 + c4;
#pragma unroll 16
    for (int k = 0; k < 16; k++) {
        float4 w = __ldg(wp + (size_t)k * n4);
        float x0 = __ldg(emb + k0 + k);
        float x1 = __ldg(emb + 1024 + k0 + k);
        s0.x += x0 * w.x; s0.y += x0 * w.y; s0.z += x0 * w.z; s0.w += x0 * w.w;
        s1.x += x1 * w.x; s1.y += x1 * w.y; s1.z += x1 * w.z; s1.w += x1 * w.w;
    }
    ((float4*)pseg)[(size_t)(kb * 2 + 0) * n4 + c4] = s0;
    ((float4*)pseg)[(size_t)(kb * 2 + 1) * n4 + c4] = s1;
}

__global__ void __launch_bounds__(256) gemm2_reduce_all(
    const float* __restrict__ part,
    const float* __restrict__ ada_b, const float* __restrict__ adaf_b,
    float* __restrict__ modsall)
{
    int z = blockIdx.z;
    int N = (z < 4) ? 6144 : 2048;
    int n4 = N >> 2;
    int i = blockIdx.x * 256 + threadIdx.x;
    if (i >= 2 * n4) return;
    const float* pseg = part + (size_t)z * 64 * 2 * 6144;
    const float* bias = (z < 4) ? (ada_b + z * 6144) : adaf_b;
    float* out = modsall + (size_t)z * 2 * 6144;

    int row = (i >= n4) ? 1 : 0;
    int c4 = i - row * n4;
    float4 s = ((const float4*)bias)[c4];
#pragma unroll 16
    for (int kb = 0; kb < 64; kb++) {
        float4 p = ((const float4*)pseg)[(size_t)(kb * 2 + row) * n4 + c4];
        s.x += p.x; s.y += p.y; s.z += p.z; s.w += p.w;
    }
    ((float4*)out)[(size_t)row * n4 + c4] = s;
}

// ---------------------------------------------------------------------------
// LayerNorm + adaLN modulate; fp16 out
// ---------------------------------------------------------------------------
template <bool AFF>
__global__ void __launch_bounds__(256) ln_mod_kernel(
    const float* __restrict__ x, const float* __restrict__ w,
    const float* __restrict__ bvec, const float* __restrict__ mods,
    int mstride, int sc_off, int sh_off, float eps, __half* __restrict__ out)
{
    __shared__ float red[8];
    const int t = blockIdx.x;
    const int bb = t >> 10;
    const int tid = threadIdx.x;
    const float* xr = x + (size_t)t * EDIM;

    float4 v = *(const float4*)(xr + tid * 4);
    float s = v.x + v.y + v.z + v.w;
    s = warp_sum(s);
    if ((tid & 31) == 0) red[tid >> 5] = s;
    __syncthreads();
    float tot = 0.f;
#pragma unroll
    for (int i = 0; i < 8; i++) tot += red[i];
    float mean = tot * (1.f / 1024.f);
    __syncthreads();

    float dx = v.x - mean, dy = v.y - mean, dz = v.z - mean, dw = v.w - mean;
    float q = dx * dx + dy * dy + dz * dz + dw * dw;
    q = warp_sum(q);
    if ((tid & 31) == 0) red[tid >> 5] = q;
    __syncthreads();
    float vq = 0.f;
#pragma unroll
    for (int i = 0; i < 8; i++) vq += red[i];
    float inv = rsqrtf(vq * (1.f / 1024.f) + eps);

    float4 msc = *(const float4*)(mods + bb * mstride + sc_off + tid * 4);
    float4 msh = *(const float4*)(mods + bb * mstride + sh_off + tid * 4);
    float yv[4] = { dx * inv, dy * inv, dz * inv, dw * inv };
    float sc[4] = { msc.x, msc.y, msc.z, msc.w };
    float sh[4] = { msh.x, msh.y, msh.z, msh.w };
    __half hv[4];
#pragma unroll
    for (int i = 0; i < 4; i++) {
        int c = tid * 4 + i;
        float y = yv[i];
        if (AFF) y = y * w[c] + bvec[c];
        y = y * (1.f + sc[i]) + sh[i];
        hv[i] = __float2half(y);
    }
    *(uint2*)(out + (size_t)t * EDIM + tid * 4) = *(uint2*)hv;
}

// ---------------------------------------------------------------------------
// FP16 flash attention, BM=128 (8 warps), fused rotary.
// Qh[128][72], Kh[64][72], Ph[128][72], Vh[64][136].
// ---------------------------------------------------------------------------
#define FT_SMEM ((128 * 72 + 64 * 72 + 128 * 72 + 64 * 136) * 2)

__global__ void __launch_bounds__(256) flash_h_kernel(
    const __half* __restrict__ qkv, __half* __restrict__ a1, __half* __restrict__ a2)
{
    extern __shared__ __half fsm[];
    __half* Qh = fsm;                  // [128][72]
    __half* Kh = Qh + 128 * 72;        // [64][72]
    __half* Ph = Kh + 64 * 72;         // [128][72]
    __half* Vh = Ph + 128 * 72;        // [64][136]

    const int it  = (int)gridDim.x - 1 - (int)blockIdx.x;   // 0..7 heavy-first
    const int h16 = blockIdx.y;
    const int b   = blockIdx.z;
    const int h   = h16 >> 1;
    const int tid = threadIdx.x;
    const int wid = tid >> 5, lane = tid & 31;
    const int g = lane >> 2, t = lane & 3;
    const int i0 = it * 128;
    const int m0 = wid * 16;

    const __half* qb = qkv + (size_t)b * SLEN * 3072 + h16 * 64;
    const __half* kb = qb + 1024;
    const __half* vb = qkv + (size_t)b * SLEN * 3072 + 2048 + h * 128;
    __half* ob = ((h16 & 1) ? a2 : a1) + (size_t)b * SLEN * EDIM + h * 128;

    const uint32_t q_u = (uint32_t)__cvta_generic_to_shared(Qh);
    const uint32_t k_u = (uint32_t)__cvta_generic_to_shared(Kh);
    const uint32_t p_u = (uint32_t)__cvta_generic_to_shared(Ph);
    const uint32_t v_u = (uint32_t)__cvta_generic_to_shared(Vh);

    const int a_row = lane & 15;
    const int a_col = (lane >> 4) << 3;
    const int b_row = (lane & 7) + ((lane & 16) >> 1);
    const int b_col = lane & 8;

    // Q tile: 128 rows x 8 chunks, fused rotary
#pragma unroll
    for (int u = 0; u < 4; u++) {
        int l = tid + u * 256;
        int r = l >> 3, c = (l & 7) * 8;
        uint4 uu = *(const uint4*)(qb + (size_t)(i0 + r) * 3072 + c);
        if (c < 32) {
            __half2* hp = reinterpret_cast<__half2*>(&uu);
            float s = (float)(i0 + r);
#pragma unroll
            for (int p = 0; p < 4; p++) {
                int j = (c >> 1) + p;
                float inv = exp2f(-(float)(2 * j) * (13.2877123795494f / 32.f));
                float f = s * inv;
                float sf, cf;
                sincosf(f, &sf, &cf);
                float2 xv = __half22float2(hp[p]);
                hp[p] = __floats2half2_rn(xv.x * cf - xv.y * sf,
                                          xv.y * cf + xv.x * sf);
            }
        }
        *(uint4*)(Qh + r * 72 + c) = uu;
    }

    float mrow0 = -1e30f, mrow1 = -1e30f, lrow0 = 0.f, lrow1 = 0.f;
    float oacc[16][4];
#pragma unroll
    for (int nt = 0; nt < 16; nt++)
#pragma unroll
        for (int r = 0; r < 4; r++) oacc[nt][r] = 0.f;

    __syncthreads();

    const int njt = 2 * it + 2;
    for (int jt = 0; jt < njt; jt++) {
        int j0 = jt * 64;
        // K tile (64 rows) with fused rotary
#pragma unroll
        for (int u = 0; u < 2; u++) {
            int l = tid + u * 256;
            int r = l >> 3, c = (l & 7) * 8;
            uint4 uu = *(const uint4*)(kb + (size_t)(j0 + r) * 3072 + c);
            if (c < 32) {
                __half2* hp = reinterpret_cast<__half2*>(&uu);
                float s = (float)(j0 + r);
#pragma unroll
                for (int p = 0; p < 4; p++) {
                    int j = (c >> 1) + p;
                    float inv = exp2f(-(float)(2 * j) * (13.2877123795494f / 32.f));
                    float f = s * inv;
                    float sf, cf;
                    sincosf(f, &sf, &cf);
                    float2 xv = __half22float2(hp[p]);
                    hp[p] = __floats2half2_rn(xv.x * cf - xv.y * sf,
                                              xv.y * cf + xv.x * sf);
                }
            }
            *(uint4*)(Kh + r * 72 + c) = uu;
        }
        // V tile: 64 rows x 16 chunks
#pragma unroll
        for (int u = 0; u < 4; u++) {
            int l = tid + u * 256;
            int r = l >> 4, c = (l & 15) * 8;
            *(uint4*)(Vh + r * 136 + c) =
                *(const uint4*)(vb + (size_t)(j0 + r) * 3072 + c);
        }
        __syncthreads();

        float sacc[8][4];
#pragma unroll
        for (int nt = 0; nt < 8; nt++)
#pragma unroll
            for (int r = 0; r < 4; r++) sacc[nt][r] = 0.f;

#pragma unroll
        for (int ks = 0; ks < 64; ks += 16) {
            uint32_t a[4];
            ldsm_x4(a, q_u + 2 * ((m0 + a_row) * 72 + a_col + ks));
#pragma unroll
            for (int n2 = 0; n2 < 4; n2++) {
                uint32_t bq[4];
                ldsm_x4(bq, k_u + 2 * ((n2 * 16 + b_row) * 72 + b_col + ks));
#pragma unroll
                for (int hh = 0; hh < 2; hh++) {
                    uint32_t bb[2] = { bq[2 * hh], bq[2 * hh + 1] };
                    mma_f16(sacc[n2 * 2 + hh], a, bb);
                }
            }
        }

        const int row0 = i0 + m0 + g, row1 = row0 + 8;
        float tm0 = -1e30f, tm1 = -1e30f;
#pragma unroll
        for (int nt = 0; nt < 8; nt++) {
            int c0 = j0 + nt * 8 + 2 * t;
            sacc[nt][0] = (c0     <= row0) ? sacc[nt][0] * 0.125f : -1e30f;
            sacc[nt][1] = (c0 + 1 <= row0) ? sacc[nt][1] * 0.125f : -1e30f;
            sacc[nt][2] = (c0     <= row1) ? sacc[nt][2] * 0.125f : -1e30f;
            sacc[nt][3] = (c0 + 1 <= row1) ? sacc[nt][3] * 0.125f : -1e30f;
            tm0 = fmaxf(tm0, fmaxf(sacc[nt][0], sacc[nt][1]));
            tm1 = fmaxf(tm1, fmaxf(sacc[nt][2], sacc[nt][3]));
        }
        tm0 = fmaxf(tm0, __shfl_xor_sync(0xffffffffu, tm0, 1));
        tm0 = fmaxf(tm0, __shfl_xor_sync(0xffffffffu, tm0, 2));
        tm1 = fmaxf(tm1, __shfl_xor_sync(0xffffffffu, tm1, 1));
        tm1 = fmaxf(tm1, __shfl_xor_sync(0xffffffffu, tm1, 2));

        float nm0 = fmaxf(mrow0, tm0), nm1 = fmaxf(mrow1, tm1);
        float f0 = __expf(mrow0 - nm0), f1 = __expf(mrow1 - nm1);
        mrow0 = nm0; mrow1 = nm1;

        float ts0 = 0.f, ts1 = 0.f;
#pragma unroll
        for (int nt = 0; nt < 8; nt++) {
            __half2 p0h = __floats2half2_rn(__expf(sacc[nt][0] - nm0),
                                            __expf(sacc[nt][1] - nm0));
            __half2 p1h = __floats2half2_rn(__expf(sacc[nt][2] - nm1),
                                            __expf(sacc[nt][3] - nm1));
            float2 p0f = __half22float2(p0h);
            float2 p1f = __half22float2(p1h);
            ts0 += p0f.x + p0f.y;
            ts1 += p1f.x + p1f.y;
            *reinterpret_cast<__half2*>(Ph + (m0 + g) * 72 + nt * 8 + 2 * t) = p0h;
            *reinterpret_cast<__half2*>(Ph + (m0 + 8 + g) * 72 + nt * 8 + 2 * t) = p1h;
        }
        ts0 += __shfl_xor_sync(0xffffffffu, ts0, 1);
        ts0 += __shfl_xor_sync(0xffffffffu, ts0, 2);
        ts1 += __shfl_xor_sync(0xffffffffu, ts1, 1);
        ts1 += __shfl_xor_sync(0xffffffffu, ts1, 2);
        lrow0 = lrow0 * f0 + ts0;
        lrow1 = lrow1 * f1 + ts1;

#pragma unroll
        for (int nt = 0; nt < 16; nt++) {
            oacc[nt][0] *= f0; oacc[nt][1] *= f0;
            oacc[nt][2] *= f1; oacc[nt][3] *= f1;
        }
        __syncwarp();

#pragma unroll
        for (int ks = 0; ks < 64; ks += 16) {
            uint32_t a[4];
            ldsm_x4(a, p_u + 2 * ((m0 + a_row) * 72 + a_col + ks));
#pragma unroll
            for (int n2 = 0; n2 < 8; n2++) {
                uint32_t bq[4];
                ldsm_x4_t(bq, v_u + 2 * ((ks + (lane & 15)) * 136
                                         + n2 * 16 + ((lane >> 4) << 3)));
#pragma unroll
                for (int hh = 0; hh < 2; hh++) {
                    uint32_t bb[2] = { bq[2 * hh], bq[2 * hh + 1] };
                    mma_f16(oacc[n2 * 2 + hh], a, bb);
                }
            }
        }
        __syncthreads();
    }

    float inv0 = 1.f / lrow0, inv1 = 1.f / lrow1;
#pragma unroll
    for (int nt = 0; nt < 16; nt++) {
        int c0 = nt * 8 + 2 * t;
        *reinterpret_cast<__half2*>(ob + (size_t)(i0 + m0 + g) * EDIM + c0) =
            __floats2half2_rn(oacc[nt][0] * inv0, oacc[nt][1] * inv0);
        *reinterpret_cast<__half2*>(ob + (size_t)(i0 + m0 + 8 + g) * EDIM + c0) =
            __floats2half2_rn(oacc[nt][2] * inv1, oacc[nt][3] * inv1);
    }
}

// ---------------------------------------------------------------------------
// All 4 lambda scalars
// ---------------------------------------------------------------------------
__global__ void lambda_all_kernel(
    const float* __restrict__ lq1, const float* __restrict__ lk1,
    const float* __restrict__ lq2, const float* __restrict__ lk2,
    float* __restrict__ out)
{
    int w = threadIdx.x >> 5, lid = threadIdx.x & 31;
    const float* q1 = lq1 + w * 64; const float* k1 = lk1 + w * 64;
    const float* q2 = lq2 + w * 64; const float* k2 = lk2 + w * 64;
    float s1 = q1[lid] * k1[lid] + q1[lid + 32] * k1[lid + 32];
    float s2 = q2[lid] * k2[lid] + q2[lid + 32] * k2[lid + 32];
#pragma unroll
    for (int o = 16; o; o >>= 1) {
        s1 += __shfl_xor_sync(0xffffffffu, s1, o);
        s2 += __shfl_xor_sync(0xffffffffu, s2, o);
    }
    if (lid == 0) {
        float lam_init = (float)(0.8 - 0.6 * exp(-0.3 * (double)(w + 1)));
        out[w] = expf(s1) - expf(s2) + lam_init;
    }
}

// ---------------------------------------------------------------------------
// RMS-norm of (a1 - lam*a2) per head (fp16 in); fp16 out
// ---------------------------------------------------------------------------
__global__ void __launch_bounds__(128) rmsdiff_kernel(
    const __half* __restrict__ a1, const __half* __restrict__ a2,
    const float* __restrict__ w, const float* __restrict__ bvec,
    const float* __restrict__ lamp, float oml, __half* __restrict__ out)
{
    __shared__ float red[4];
    int blk = blockIdx.x;
    int tok = blk >> 3, hh = blk & 7;
    int c = threadIdx.x;
    size_t base = (size_t)tok * EDIM + hh * 128 + c;
    float lam = lamp[0];
    float y = __half2float(a1[base]) - lam * __half2float(a2[base]);
    float q = warp_sum(y * y);
    if ((c & 31) == 0) red[c >> 5] = q;
    __syncthreads();
    float tot = red[0] + red[1] + red[2] + red[3];
    float inv = rsqrtf(tot * (1.f / 128.f) + 1e-8f);
    out[base] = __float2half((y * inv * w[c] + bvec[c]) * oml);
}

// ---------------------------------------------------------------------------
// Launch
// ---------------------------------------------------------------------------
extern "C" void kernel_launch(void* const* d_in, const int* in_sizes, int n_in,
                              void* d_out, int out_size)
{
    const float* x        = (const float*)d_in[0];
    const float* emb      = (const float*)d_in[1];
    const float* l2e_w1   = (const float*)d_in[2];
    const float* l2e_b1   = (const float*)d_in[3];
    const float* l2e_al   = (const float*)d_in[4];
    const float* l2e_be   = (const float*)d_in[5];
    const float* l2e_w2   = (const float*)d_in[6];
    const float* l2e_b2   = (const float*)d_in[7];
    const float* ln1_w    = (const float*)d_in[8];
    const float* ln1_b    = (const float*)d_in[9];
    const float* ln2_w    = (const float*)d_in[10];
    const float* ln2_b    = (const float*)d_in[11];
    const float* qkv_w    = (const float*)d_in[12];
    const float* out_w    = (const float*)d_in[13];
    const float* lq1      = (const float*)d_in[14];
    const float* lk1      = (const float*)d_in[15];
    const float* lq2      = (const float*)d_in[16];
    const float* lk2      = (const float*)d_in[17];
    const float* aln_w    = (const float*)d_in[18];
    const float* aln_b    = (const float*)d_in[19];
    const float* ada_w    = (const float*)d_in[20];
    const float* ada_b    = (const float*)d_in[21];
    const float* ff_w1    = (const float*)d_in[22];
    const float* ff_b1    = (const float*)d_in[23];
    const float* ff_al    = (const float*)d_in[24];
    const float* ff_be    = (const float*)d_in[25];
    const float* ff_w2    = (const float*)d_in[26];
    const float* ff_b2    = (const float*)d_in[27];
    const float* adaf_w   = (const float*)d_in[28];
    const float* adaf_b   = (const float*)d_in[29];
    const float* fin_w    = (const float*)d_in[30];
    const float* fin_b    = (const float*)d_in[31];

    float *h_, *modsall_, *lamv_, *part_;
    __half *th_, *hidh_, *xh_, *qkvh_, *a1h_, *a2h_;
    __half *w_l2e1, *w_l2e2, *w_qkv, *w_out, *w_ff1, *w_ff2, *w_fin;
    cudaGetSymbolAddress((void**)&h_,      g_h);
    cudaGetSymbolAddress((void**)&modsall_,g_modsall);
    cudaGetSymbolAddress((void**)&lamv_,   g_lamv);
    cudaGetSymbolAddress((void**)&part_,   g_part);
    cudaGetSymbolAddress((void**)&th_,     g_th);
    cudaGetSymbolAddress((void**)&hidh_,   g_hidh);
    cudaGetSymbolAddress((void**)&xh_,     g_xh);
    cudaGetSymbolAddress((void**)&qkvh_,   g_qkvh);
    cudaGetSymbolAddress((void**)&a1h_,    g_a1h);
    cudaGetSymbolAddress((void**)&a2h_,    g_a2h);
    cudaGetSymbolAddress((void**)&w_l2e1,  g_w_l2e1);
    cudaGetSymbolAddress((void**)&w_l2e2,  g_w_l2e2);
    cudaGetSymbolAddress((void**)&w_qkv,   g_w_qkv);
    cudaGetSymbolAddress((void**)&w_out,   g_w_out);
    cudaGetSymbolAddress((void**)&w_ff1,   g_w_ff1);
    cudaGetSymbolAddress((void**)&w_ff2,   g_w_ff2);
    cudaGetSymbolAddress((void**)&w_fin,   g_w_fin);

    cudaFuncSetAttribute(flash_h_kernel, cudaFuncAttributeMaxDynamicSharedMemorySize, FT_SMEM);
    cudaFuncSetAttribute(hgemm_kernel<0>, cudaFuncAttributeMaxDynamicSharedMemorySize, HG_SMEM);
    cudaFuncSetAttribute(hgemm_kernel<1>, cudaFuncAttributeMaxDynamicSharedMemorySize, HG_SMEM);
    cudaFuncSetAttribute(hgemm_kernel<2>, cudaFuncAttributeMaxDynamicSharedMemorySize, HG_SMEM);
    cudaFuncSetAttribute(hgemm_kernel<3>, cudaFuncAttributeMaxDynamicSharedMemorySize, HG_SMEM);

    // ---- batched convert ----
    CvtSegs segs;
    const float* ins[8]  = { l2e_w1, l2e_w2, fin_w, qkv_w, out_w, ff_w1, ff_w2, x };
    __half*      outs[8] = { w_l2e1, w_l2e2, w_fin, w_qkv, w_out, w_ff1, w_ff2, xh_ };
    size_t       ns[8]   = { (size_t)64 * EDIM, (size_t)EDIM * EDIM, (size_t)EDIM * 64,
                             (size_t)NB * EDIM * 3 * EDIM, (size_t)NB * EDIM * EDIM,
                             (size_t)NB * EDIM * E4DIM, (size_t)NB * E4DIM * EDIM,
                             (size_t)NTOK * 64 };
    int total4 = 0;
    for (int s = 0; s < 8; s++) {
        segs.in[s]  = (const float4*)ins[s];
        segs.out[s] = (uint2*)outs[s];
        segs.n4[s]  = (int)(ns[s] >> 2);
        total4 += segs.n4[s];
    }
    cvt_all_kernel<<<(total4 + 255) / 256, 256>>>(segs, total4);

    gemm2_part_all<<<dim3(12, 64, 5), 128>>>(emb, ada_w, adaf_w, part_);
    gemm2_reduce_all<<<dim3(12, 1, 5), 256>>>(part_, ada_b, adaf_b, modsall_);
    lambda_all_kernel<<<1, 128>>>(lq1, lk1, lq2, lk2, lamv_);

    auto hgN = [&](const __half* A, const __half* W, const float* bias, float* C,
                   int M, int N, int K) {
        hgemm_kernel<0><<<dim3((N + 127) / 128, M / 128), 256, HG_SMEM>>>(
            A, W, bias, C, M, N, K, nullptr, nullptr, 0);
    };
    auto hgH = [&](const __half* A, const __half* W, const float* bias, __half* C,
                   int M, int N, int K) {
        hgemm_kernel<3><<<dim3((N + 127) / 128, M / 128), 256, HG_SMEM>>>(
            A, W, bias, C, M, N, K, nullptr, nullptr, 0);
    };
    auto hgS = [&](const __half* A, const __half* W, const float* bias, __half* C,
                   int M, int N, int K, const float* al, const float* be) {
        hgemm_kernel<1><<<dim3((N + 127) / 128, M / 128), 256, HG_SMEM>>>(
            A, W, bias, C, M, N, K, al, be, 0);
    };
    auto hgG = [&](const __half* A, const __half* W, float* C,
                   int M, int N, int K, const float* bias, const float* mods, int goff) {
        hgemm_kernel<2><<<dim3((N + 127) / 128, M / 128), 256, HG_SMEM>>>(
            A, W, bias, C, M, N, K, mods, nullptr, goff);
    };

    // latent -> embedding
    hgS(xh_, w_l2e1, l2e_b1, th_, NTOK, EDIM, 64, l2e_al, l2e_be);
    hgN(th_, w_l2e2, l2e_b2, h_, NTOK, EDIM, EDIM);

    for (int i = 0; i < NB; i++) {
        float lam_init = (float)(0.8 - 0.6 * exp(-0.3 * (double)(i + 1)));
        const float* mods_i = modsall_ + (size_t)i * 2 * 6144;

        // attention half
        ln_mod_kernel<true><<<NTOK, 256>>>(h_, ln1_w + i * EDIM, ln1_b + i * EDIM,
                                           mods_i, 6144, 0, 1024, 1e-5f, th_);
        hgH(th_, w_qkv + (size_t)i * EDIM * 3072, nullptr, qkvh_, NTOK, 3072, EDIM);
        flash_h_kernel<<<dim3(8, 16, 2), 256, FT_SMEM>>>(qkvh_, a1h_, a2h_);
        rmsdiff_kernel<<<NTOK * 8, 128>>>(a1h_, a2h_, aln_w + i * 128, aln_b + i * 128,
                                          lamv_ + i, 1.f - lam_init, th_);
        hgG(th_, w_out + (size_t)i * EDIM * EDIM, h_, NTOK, EDIM, EDIM,
            nullptr, mods_i, 4096);

        // MLP half
        ln_mod_kernel<true><<<NTOK, 256>>>(h_, ln2_w + i * EDIM, ln2_b + i * EDIM,
                                           mods_i, 6144, 2048, 3072, 1e-5f, th_);
        hgS(th_, w_ff1 + (size_t)i * EDIM * E4DIM, ff_b1 + i * E4DIM, hidh_,
            NTOK, E4DIM, EDIM, ff_al + i * E4DIM, ff_be + i * E4DIM);
        hgG(hidh_, w_ff2 + (size_t)i * E4DIM * EDIM, h_, NTOK, EDIM, E4DIM,
            ff_b2 + i * EDIM, mods_i, 5120);
    }

    // final adaLN + projection
    ln_mod_kernel<false><<<NTOK, 256>>>(h_, nullptr, nullptr,
                                        modsall_ + (size_t)4 * 2 * 6144, 2048,
                                        0, 1024, 1e-6f, th_);
    hgN(th_, w_fin, fin_b, (float*)d_out, NTOK, 64, EDIM);
}

// round 15
// speedup vs baseline: 1.0311x; 1.0311x over previous
#include <cuda_runtime.h>
#include <cuda_fp16.h>
#include <math.h>
#include <stdint.h>

#define NTOK   2048
#define SLEN   1024
#define EDIM   1024
#define E4DIM  4096
#define NB     4

// ---------------------------------------------------------------------------
// Scratch
// ---------------------------------------------------------------------------
__device__ float  g_h   [NTOK * EDIM];
__device__ float  g_modsall[5 * 2 * 6144];
__device__ float  g_lamv[NB];
__device__ float  g_part[5 * 64 * 2 * 6144];
__device__ __half g_th  [NTOK * EDIM];
__device__ __half g_hidh[NTOK * E4DIM];
__device__ __half g_xh  [NTOK * 64];
__device__ __half g_qkvh[NTOK * 3 * EDIM];
__device__ __half g_a1h [NTOK * EDIM];
__device__ __half g_a2h [NTOK * EDIM];

// fp16 weights, NATURAL [K][N] layout
__device__ __half g_w_l2e1[64 * EDIM];
__device__ __half g_w_l2e2[EDIM * EDIM];
__device__ __half g_w_qkv [NB * EDIM * 3 * EDIM];
__device__ __half g_w_out [NB * EDIM * EDIM];
__device__ __half g_w_ff1 [NB * EDIM * E4DIM];
__device__ __half g_w_ff2 [NB * E4DIM * EDIM];
__device__ __half g_w_fin [EDIM * 64];

// ---------------------------------------------------------------------------
// Helpers
// ---------------------------------------------------------------------------
__device__ __forceinline__ float warp_sum(float v) {
#pragma unroll
    for (int o = 16; o; o >>= 1) v += __shfl_xor_sync(0xffffffffu, v, o);
    return v;
}

__device__ __forceinline__ void mma_f16(
    float* c, const uint32_t* a, const uint32_t* b)
{
    asm volatile(
        "mma.sync.aligned.m16n8k16.row.col.f32.f16.f16.f32 "
        "{%0,%1,%2,%3}, {%4,%5,%6,%7}, {%8,%9}, {%0,%1,%2,%3};"
        : "+f"(c[0]), "+f"(c[1]), "+f"(c[2]), "+f"(c[3])
        : "r"(a[0]), "r"(a[1]), "r"(a[2]), "r"(a[3]),
          "r"(b[0]), "r"(b[1]));
}

__device__ __forceinline__ void ldsm_x4(uint32_t* r, uint32_t addr) {
    asm volatile("ldmatrix.sync.aligned.m8n8.x4.shared.b16 {%0,%1,%2,%3}, [%4];"
        : "=r"(r[0]), "=r"(r[1]), "=r"(r[2]), "=r"(r[3]) : "r"(addr));
}
__device__ __forceinline__ void ldsm_x4_t(uint32_t* r, uint32_t addr) {
    asm volatile("ldmatrix.sync.aligned.m8n8.x4.trans.shared.b16 {%0,%1,%2,%3}, [%4];"
        : "=r"(r[0]), "=r"(r[1]), "=r"(r[2]), "=r"(r[3]) : "r"(addr));
}

__device__ __forceinline__ void cp_async16(void* smem, const void* gmem) {
    uint32_t s = (uint32_t)__cvta_generic_to_shared(smem);
    asm volatile("cp.async.cg.shared.global [%0], [%1], 16;"
                 :: "r"(s), "l"(gmem));
}
__device__ __forceinline__ void cp_async16_pred(void* smem, const void* gmem, bool p) {
    uint32_t s = (uint32_t)__cvta_generic_to_shared(smem);
    int sz = p ? 16 : 0;
    asm volatile("cp.async.cg.shared.global [%0], [%1], 16, %2;"
                 :: "r"(s), "l"(gmem), "r"(sz));
}
#define CP_COMMIT() asm volatile("cp.async.commit_group;" ::: "memory")
#define CP_WAIT1()  asm volatile("cp.async.wait_group 1;" ::: "memory")

// ---------------------------------------------------------------------------
// Batched fp32 -> fp16 convert over 8 segments (one launch)
// ---------------------------------------------------------------------------
struct CvtSegs {
    const float4* in[8];
    uint2*        out[8];
    int           n4[8];
};

__global__ void __launch_bounds__(256) cvt_all_kernel(CvtSegs segs, int total4)
{
    int i = blockIdx.x * 256 + threadIdx.x;
    if (i >= total4) return;
    int seg = 0, off = i;
#pragma unroll
    for (int s = 0; s < 8; s++) {
        if (off >= segs.n4[s]) { off -= segs.n4[s]; seg++; }
        else break;
    }
    float4 v = __ldg(segs.in[seg] + off);
    uint2 u;
    *reinterpret_cast<__half2*>(&u.x) = __floats2half2_rn(v.x, v.y);
    *reinterpret_cast<__half2*>(&u.y) = __floats2half2_rn(v.z, v.w);
    segs.out[seg][off] = u;
}

// ---------------------------------------------------------------------------
// FP16 tensor-core GEMM (mma.m16n8k16, ldmatrix A non-trans, B trans).
// BK=64, 2-stage cp.async. See R12/R13.
// ---------------------------------------------------------------------------
#define HG_ASZ   (128 * 72)
#define HG_BSZ   (64 * 136)
#define HG_SMEM  ((2 * HG_ASZ + 2 * HG_BSZ) * 2)

template <int MODE>
__global__ void __launch_bounds__(256) hgemm_kernel(
    const __half* __restrict__ A, const __half* __restrict__ W,
    const float* __restrict__ bias, void* __restrict__ Cv,
    int M, int N, int K,
    const float* __restrict__ p1, const float* __restrict__ p2, int goff)
{
    extern __shared__ __half hsm[];
    __half* As = hsm;
    __half* Bs = hsm + 2 * HG_ASZ;

    const int bm  = blockIdx.y * 128;
    const int bn  = blockIdx.x * 128;
    const int tid = threadIdx.x;
    const int wid = tid >> 5, lane = tid & 31;
    const int g = lane >> 2, t = lane & 3;
    const int wm = (wid >> 2) * 64;
    const int wn = (wid & 3) * 32;

    const int KT = K >> 6;

    const int a_row = lane & 15;
    const int a_col = (lane >> 4) << 3;
    const int b_kr  = lane & 15;
    const int b_nc  = (lane >> 4) << 3;

    const uint32_t as_u = (uint32_t)__cvta_generic_to_shared(As);
    const uint32_t bs_u = (uint32_t)__cvta_generic_to_shared(Bs);

    auto load_stage = [&](int s, int k0) {
        __half* as = As + s * HG_ASZ;
        __half* bs = Bs + s * HG_BSZ;
#pragma unroll
        for (int u = 0; u < 4; u++) {
            int l = tid + u * 256;
            int r = l >> 3, c = (l & 7) * 8;
            cp_async16(as + r * 72 + c, A + (size_t)(bm + r) * K + k0 + c);
        }
#pragma unroll
        for (int u = 0; u < 4; u++) {
            int l = tid + u * 256;
            int r = l >> 4, c = (l & 15) * 8;
            bool ok = (bn + c) < N;
            cp_async16_pred(bs + r * 136 + c,
                            W + (size_t)(k0 + r) * N + (ok ? (bn + c) : 0), ok);
        }
    };

    float acc[4][4][4];
#pragma unroll
    for (int mt = 0; mt < 4; mt++)
#pragma unroll
        for (int nt = 0; nt < 4; nt++)
#pragma unroll
            for (int r = 0; r < 4; r++) acc[mt][nt][r] = 0.f;

    load_stage(0, 0);
    CP_COMMIT();

    for (int ki = 0; ki < KT; ki++) {
        if (ki + 1 < KT) load_stage((ki + 1) & 1, (ki + 1) * 64);
        CP_COMMIT();
        CP_WAIT1();
        __syncthreads();

        const uint32_t asb = as_u + (ki & 1) * HG_ASZ * 2;
        const uint32_t bsb = bs_u + (ki & 1) * HG_BSZ * 2;
#pragma unroll
        for (int ks = 0; ks < 64; ks += 16) {
            uint32_t a[4][4], bq[2][4];
#pragma unroll
            for (int mt = 0; mt < 4; mt++)
                ldsm_x4(a[mt], asb + 2 * ((wm + mt * 16 + a_row) * 72 + a_col + ks));
#pragma unroll
            for (int n2 = 0; n2 < 2; n2++)
                ldsm_x4_t(bq[n2], bsb + 2 * ((ks + b_kr) * 136 + wn + n2 * 16 + b_nc));
#pragma unroll
            for (int n2 = 0; n2 < 2; n2++)
#pragma unroll
                for (int hh = 0; hh < 2; hh++) {
                    uint32_t bb[2] = { bq[n2][2 * hh], bq[n2][2 * hh + 1] };
#pragma unroll
                    for (int mt = 0; mt < 4; mt++)
                        mma_f16(acc[mt][n2 * 2 + hh], a[mt], bb);
                }
        }
        __syncthreads();
    }

    float*  Cf = (float*)Cv;
    __half* Ch = (__half*)Cv;
#pragma unroll
    for (int mt = 0; mt < 4; mt++) {
        int r0 = bm + wm + mt * 16 + g;
#pragma unroll
        for (int nt = 0; nt < 4; nt++) {
            int c0 = bn + wn + nt * 8 + 2 * t;
            if (c0 < N) {
#pragma unroll
                for (int half_ = 0; half_ < 2; half_++) {
                    int rr = r0 + half_ * 8;
#pragma unroll
                    for (int e = 0; e < 2; e++) {
                        int cc = c0 + e;
                        float v = acc[mt][nt][half_ * 2 + e];
                        if (bias) v += bias[cc];
                        if (MODE == 1) {
                            float sn = __sinf(p1[cc] * v);
                            v += sn * sn / (p2[cc] + 1e-9f);
                            Ch[(size_t)rr * N + cc] = __float2half(v);
                        } else if (MODE == 2) {
                            int bb = rr >> 10;
                            float gg = p1[bb * 6144 + goff + cc];
                            float sg = 1.f / (1.f + __expf(gg - 1.f));
                            Cf[(size_t)rr * N + cc] += v * sg;
                        } else if (MODE == 3) {
                            Ch[(size_t)rr * N + cc] = __float2half(v);
                        } else {
                            Cf[(size_t)rr * N + cc] = v;
                        }
                    }
                }
            }
        }
    }
}

// ---------------------------------------------------------------------------
// Batched small-M GEMM (M=2): 5 segments, 64-way K split
// ---------------------------------------------------------------------------
__global__ void __launch_bounds__(128) gemm2_part_all(
    const float* __restrict__ emb,
    const float* __restrict__ ada_w, const float* __restrict__ adaf_w,
    float* __restrict__ part)
{
    int z = blockIdx.z;
    int N = (z < 4) ? 6144 : 2048;
    if (blockIdx.x * 512 >= N) return;
    const float* W = (z < 4) ? (ada_w + (size_t)z * EDIM * 6144) : adaf_w;
    float* pseg = part + (size_t)z * 64 * 2 * 6144;

    int n4 = N >> 2;
    int c4 = blockIdx.x * 128 + threadIdx.x;
    int kb = blockIdx.y, k0 = kb * 16;
    float4 s0 = make_float4(0.f, 0.f, 0.f, 0.f);
    float4 s1 = make_float4(0.f, 0.f, 0.f, 0.f);
    const float4* wp = (const float4*)W + (size_t)k0 * n4 + c4;
#pragma unroll 16
    for (int k = 0; k < 16; k++) {
        float4 w = __ldg(wp + (size_t)k * n4);
        float x0 = __ldg(emb + k0 + k);
        float x1 = __ldg(emb + 1024 + k0 + k);
        s0.x += x0 * w.x; s0.y += x0 * w.y; s0.z += x0 * w.z; s0.w += x0 * w.w;
        s1.x += x1 * w.x; s1.y += x1 * w.y; s1.z += x1 * w.z; s1.w += x1 * w.w;
    }
    ((float4*)pseg)[(size_t)(kb * 2 + 0) * n4 + c4] = s0;
    ((float4*)pseg)[(size_t)(kb * 2 + 1) * n4 + c4] = s1;
}

__global__ void __launch_bounds__(256) gemm2_reduce_all(
    const float* __restrict__ part,
    const float* __restrict__ ada_b, const float* __restrict__ adaf_b,
    float* __restrict__ modsall)
{
    int z = blockIdx.z;
    int N = (z < 4) ? 6144 : 2048;
    int n4 = N >> 2;
    int i = blockIdx.x * 256 + threadIdx.x;
    if (i >= 2 * n4) return;
    const float* pseg = part + (size_t)z * 64 * 2 * 6144;
    const float* bias = (z < 4) ? (ada_b + z * 6144) : adaf_b;
    float* out = modsall + (size_t)z * 2 * 6144;

    int row = (i >= n4) ? 1 : 0;
    int c4 = i - row * n4;
    float4 s = ((const float4*)bias)[c4];
#pragma unroll 16
    for (int kb = 0; kb < 64; kb++) {
        float4 p = ((const float4*)pseg)[(size_t)(kb * 2 + row) * n4 + c4];
        s.x += p.x; s.y += p.y; s.z += p.z; s.w += p.w;
    }
    ((float4*)out)[(size_t)row * n4 + c4] = s;
}

// ---------------------------------------------------------------------------
// LayerNorm + adaLN modulate; fp16 out
// ---------------------------------------------------------------------------
template <bool AFF>
__global__ void __launch_bounds__(256) ln_mod_kernel(
    const float* __restrict__ x, const float* __restrict__ w,
    const float* __restrict__ bvec, const float* __restrict__ mods,
    int mstride, int sc_off, int sh_off, float eps, __half* __restrict__ out)
{
    __shared__ float red[8];
    const int t = blockIdx.x;
    const int bb = t >> 10;
    const int tid = threadIdx.x;
    const float* xr = x + (size_t)t * EDIM;

    float4 v = *(const float4*)(xr + tid * 4);
    float s = v.x + v.y + v.z + v.w;
    s = warp_sum(s);
    if ((tid & 31) == 0) red[tid >> 5] = s;
    __syncthreads();
    float tot = 0.f;
#pragma unroll
    for (int i = 0; i < 8; i++) tot += red[i];
    float mean = tot * (1.f / 1024.f);
    __syncthreads();

    float dx = v.x - mean, dy = v.y - mean, dz = v.z - mean, dw = v.w - mean;
    float q = dx * dx + dy * dy + dz * dz + dw * dw;
    q = warp_sum(q);
    if ((tid & 31) == 0) red[tid >> 5] = q;
    __syncthreads();
    float vq = 0.f;
#pragma unroll
    for (int i = 0; i < 8; i++) vq += red[i];
    float inv = rsqrtf(vq * (1.f / 1024.f) + eps);

    float4 msc = *(const float4*)(mods + bb * mstride + sc_off + tid * 4);
    float4 msh = *(const float4*)(mods + bb * mstride + sh_off + tid * 4);
    float yv[4] = { dx * inv, dy * inv, dz * inv, dw * inv };
    float sc[4] = { msc.x, msc.y, msc.z, msc.w };
    float sh[4] = { msh.x, msh.y, msh.z, msh.w };
    __half hv[4];
#pragma unroll
    for (int i = 0; i < 4; i++) {
        int c = tid * 4 + i;
        float y = yv[i];
        if (AFF) y = y * w[c] + bvec[c];
        y = y * (1.f + sc[i]) + sh[i];
        hv[i] = __float2half(y);
    }
    *(uint2*)(out + (size_t)t * EDIM + tid * 4) = *(uint2*)hv;
}

// ---------------------------------------------------------------------------
// FP16 flash attention (BM=64, 4 warps) with fused rotary — R13 version.
// ---------------------------------------------------------------------------
#define FT_SMEM ((64 * 72 * 3 + 64 * 136) * 2)

__global__ void __launch_bounds__(128) flash_h_kernel(
    const __half* __restrict__ qkv, __half* __restrict__ a1, __half* __restrict__ a2)
{
    extern __shared__ __half fsm[];
    __half* Qh = fsm;
    __half* Kh = Qh + 64 * 72;
    __half* Ph = Kh + 64 * 72;
    __half* Vh = Ph + 64 * 72;

    const int it  = (int)gridDim.x - 1 - (int)blockIdx.x;
    const int h16 = blockIdx.y;
    const int b   = blockIdx.z;
    const int h   = h16 >> 1;
    const int tid = threadIdx.x;
    const int wid = tid >> 5, lane = tid & 31;
    const int g = lane >> 2, t = lane & 3;
    const int i0 = it * 64;
    const int m0 = wid * 16;

    const __half* qb = qkv + (size_t)b * SLEN * 3072 + h16 * 64;
    const __half* kb = qb + 1024;
    const __half* vb = qkv + (size_t)b * SLEN * 3072 + 2048 + h * 128;
    __half* ob = ((h16 & 1) ? a2 : a1) + (size_t)b * SLEN * EDIM + h * 128;

    const uint32_t q_u = (uint32_t)__cvta_generic_to_shared(Qh);
    const uint32_t k_u = (uint32_t)__cvta_generic_to_shared(Kh);
    const uint32_t p_u = (uint32_t)__cvta_generic_to_shared(Ph);
    const uint32_t v_u = (uint32_t)__cvta_generic_to_shared(Vh);

    const int a_row = lane & 15;
    const int a_col = (lane >> 4) << 3;
    const int b_row = (lane & 7) + ((lane & 16) >> 1);
    const int b_col = lane & 8;

#pragma unroll
    for (int u = 0; u < 4; u++) {
        int l = tid + u * 128;
        int r = l >> 3, c = (l & 7) * 8;
        uint4 uu = *(const uint4*)(qb + (size_t)(i0 + r) * 3072 + c);
        if (c < 32) {
            __half2* hp = reinterpret_cast<__half2*>(&uu);
            float s = (float)(i0 + r);
#pragma unroll
            for (int p = 0; p < 4; p++) {
                int j = (c >> 1) + p;
                float inv = exp2f(-(float)(2 * j) * (13.2877123795494f / 32.f));
                float f = s * inv;
                float sf, cf;
                sincosf(f, &sf, &cf);
                float2 xv = __half22float2(hp[p]);
                hp[p] = __floats2half2_rn(xv.x * cf - xv.y * sf,
                                          xv.y * cf + xv.x * sf);
            }
        }
        *(uint4*)(Qh + r * 72 + c) = uu;
    }

    float mrow0 = -1e30f, mrow1 = -1e30f, lrow0 = 0.f, lrow1 = 0.f;
    float oacc[16][4];
#pragma unroll
    for (int nt = 0; nt < 16; nt++)
#pragma unroll
        for (int r = 0; r < 4; r++) oacc[nt][r] = 0.f;

    __syncthreads();

    for (int jt = 0; jt <= it; jt++) {
        int j0 = jt * 64;
#pragma unroll
        for (int u = 0; u < 4; u++) {
            int l = tid + u * 128;
            int r = l >> 3, c = (l & 7) * 8;
            uint4 uu = *(const uint4*)(kb + (size_t)(j0 + r) * 3072 + c);
            if (c < 32) {
                __half2* hp = reinterpret_cast<__half2*>(&uu);
                float s = (float)(j0 + r);
#pragma unroll
                for (int p = 0; p < 4; p++) {
                    int j = (c >> 1) + p;
                    float inv = exp2f(-(float)(2 * j) * (13.2877123795494f / 32.f));
                    float f = s * inv;
                    float sf, cf;
                    sincosf(f, &sf, &cf);
                    float2 xv = __half22float2(hp[p]);
                    hp[p] = __floats2half2_rn(xv.x * cf - xv.y * sf,
                                              xv.y * cf + xv.x * sf);
                }
            }
            *(uint4*)(Kh + r * 72 + c) = uu;
        }
#pragma unroll
        for (int u = 0; u < 8; u++) {
            int l = tid + u * 128;
            int r = l >> 4, c = (l & 15) * 8;
            *(uint4*)(Vh + r * 136 + c) =
                *(const uint4*)(vb + (size_t)(j0 + r) * 3072 + c);
        }
        __syncthreads();

        float sacc[8][4];
#pragma unroll
        for (int nt = 0; nt < 8; nt++)
#pragma unroll
            for (int r = 0; r < 4; r++) sacc[nt][r] = 0.f;

#pragma unroll
        for (int ks = 0; ks < 64; ks += 16) {
            uint32_t a[4];
            ldsm_x4(a, q_u + 2 * ((m0 + a_row) * 72 + a_col + ks));
#pragma unroll
            for (int n2 = 0; n2 < 4; n2++) {
                uint32_t bq[4];
                ldsm_x4(bq, k_u + 2 * ((n2 * 16 + b_row) * 72 + b_col + ks));
#pragma unroll
                for (int hh = 0; hh < 2; hh++) {
                    uint32_t bb[2] = { bq[2 * hh], bq[2 * hh + 1] };
                    mma_f16(sacc[n2 * 2 + hh], a, bb);
                }
            }
        }

        const int row0 = i0 + m0 + g, row1 = row0 + 8;
        float tm0 = -1e30f, tm1 = -1e30f;
#pragma unroll
        for (int nt = 0; nt < 8; nt++) {
            int c0 = j0 + nt * 8 + 2 * t;
            sacc[nt][0] = (c0     <= row0) ? sacc[nt][0] * 0.125f : -1e30f;
            sacc[nt][1] = (c0 + 1 <= row0) ? sacc[nt][1] * 0.125f : -1e30f;
            sacc[nt][2] = (c0     <= row1) ? sacc[nt][2] * 0.125f : -1e30f;
            sacc[nt][3] = (c0 + 1 <= row1) ? sacc[nt][3] * 0.125f : -1e30f;
            tm0 = fmaxf(tm0, fmaxf(sacc[nt][0], sacc[nt][1]));
            tm1 = fmaxf(tm1, fmaxf(sacc[nt][2], sacc[nt][3]));
        }
        tm0 = fmaxf(tm0, __shfl_xor_sync(0xffffffffu, tm0, 1));
        tm0 = fmaxf(tm0, __shfl_xor_sync(0xffffffffu, tm0, 2));
        tm1 = fmaxf(tm1, __shfl_xor_sync(0xffffffffu, tm1, 1));
        tm1 = fmaxf(tm1, __shfl_xor_sync(0xffffffffu, tm1, 2));

        float nm0 = fmaxf(mrow0, tm0), nm1 = fmaxf(mrow1, tm1);
        float f0 = __expf(mrow0 - nm0), f1 = __expf(mrow1 - nm1);
        mrow0 = nm0; mrow1 = nm1;

        float ts0 = 0.f, ts1 = 0.f;
#pragma unroll
        for (int nt = 0; nt < 8; nt++) {
            __half2 p0h = __floats2half2_rn(__expf(sacc[nt][0] - nm0),
                                            __expf(sacc[nt][1] - nm0));
            __half2 p1h = __floats2half2_rn(__expf(sacc[nt][2] - nm1),
                                            __expf(sacc[nt][3] - nm1));
            float2 p0f = __half22float2(p0h);
            float2 p1f = __half22float2(p1h);
            ts0 += p0f.x + p0f.y;
            ts1 += p1f.x + p1f.y;
            *reinterpret_cast<__half2*>(Ph + (m0 + g) * 72 + nt * 8 + 2 * t) = p0h;
            *reinterpret_cast<__half2*>(Ph + (m0 + 8 + g) * 72 + nt * 8 + 2 * t) = p1h;
        }
        ts0 += __shfl_xor_sync(0xffffffffu, ts0, 1);
        ts0 += __shfl_xor_sync(0xffffffffu, ts0, 2);
        ts1 += __shfl_xor_sync(0xffffffffu, ts1, 1);
        ts1 += __shfl_xor_sync(0xffffffffu, ts1, 2);
        lrow0 = lrow0 * f0 + ts0;
        lrow1 = lrow1 * f1 + ts1;

#pragma unroll
        for (int nt = 0; nt < 16; nt++) {
            oacc[nt][0] *= f0; oacc[nt][1] *= f0;
            oacc[nt][2] *= f1; oacc[nt][3] *= f1;
        }
        __syncwarp();

#pragma unroll
        for (int ks = 0; ks < 64; ks += 16) {
            uint32_t a[4];
            ldsm_x4(a, p_u + 2 * ((m0 + a_row) * 72 + a_col + ks));
#pragma unroll
            for (int n2 = 0; n2 < 8; n2++) {
                uint32_t bq[4];
                ldsm_x4_t(bq, v_u + 2 * ((ks + (lane & 15)) * 136
                                         + n2 * 16 + ((lane >> 4) << 3)));
#pragma unroll
                for (int hh = 0; hh < 2; hh++) {
                    uint32_t bb[2] = { bq[2 * hh], bq[2 * hh + 1] };
                    mma_f16(oacc[n2 * 2 + hh], a, bb);
                }
            }
        }
        __syncthreads();
    }

    float inv0 = 1.f / lrow0, inv1 = 1.f / lrow1;
#pragma unroll
    for (int nt = 0; nt < 16; nt++) {
        int c0 = nt * 8 + 2 * t;
        *reinterpret_cast<__half2*>(ob + (size_t)(i0 + m0 + g) * EDIM + c0) =
            __floats2half2_rn(oacc[nt][0] * inv0, oacc[nt][1] * inv0);
        *reinterpret_cast<__half2*>(ob + (size_t)(i0 + m0 + 8 + g) * EDIM + c0) =
            __floats2half2_rn(oacc[nt][2] * inv1, oacc[nt][3] * inv1);
    }
}

// ---------------------------------------------------------------------------
// All 4 lambda scalars
// ---------------------------------------------------------------------------
__global__ void lambda_all_kernel(
    const float* __restrict__ lq1, const float* __restrict__ lk1,
    const float* __restrict__ lq2, const float* __restrict__ lk2,
    float* __restrict__ out)
{
    int w = threadIdx.x >> 5, lid = threadIdx.x & 31;
    const float* q1 = lq1 + w * 64; const float* k1 = lk1 + w * 64;
    const float* q2 = lq2 + w * 64; const float* k2 = lk2 + w * 64;
    float s1 = q1[lid] * k1[lid] + q1[lid + 32] * k1[lid + 32];
    float s2 = q2[lid] * k2[lid] + q2[lid + 32] * k2[lid + 32];
#pragma unroll
    for (int o = 16; o; o >>= 1) {
        s1 += __shfl_xor_sync(0xffffffffu, s1, o);
        s2 += __shfl_xor_sync(0xffffffffu, s2, o);
    }
    if (lid == 0) {
        float lam_init = (float)(0.8 - 0.6 * exp(-0.3 * (double)(w + 1)));
        out[w] = expf(s1) - expf(s2) + lam_init;
    }
}

// ---------------------------------------------------------------------------
// RMS-norm of (a1 - lam*a2): one block per token, one warp per head.
// Lane l of warp hh owns elems hh*128 + 4l .. +3 (uint2 fp16 loads).
// ---------------------------------------------------------------------------
__global__ void __launch_bounds__(256) rmsdiff_kernel(
    const __half* __restrict__ a1, const __half* __restrict__ a2,
    const float* __restrict__ w, const float* __restrict__ bvec,
    const float* __restrict__ lamp, float oml, __half* __restrict__ out)
{
    int tok = blockIdx.x;
    int hh = threadIdx.x >> 5, lid = threadIdx.x & 31;
    int c = lid * 4;                           // within-head col
    size_t base = (size_t)tok * EDIM + hh * 128 + c;
    float lam = lamp[0];

    uint2 u1 = *(const uint2*)(a1 + base);
    uint2 u2 = *(const uint2*)(a2 + base);
    float2 p10 = __half22float2(*reinterpret_cast<__half2*>(&u1.x));
    float2 p11 = __half22float2(*reinterpret_cast<__half2*>(&u1.y));
    float2 p20 = __half22float2(*reinterpret_cast<__half2*>(&u2.x));
    float2 p21 = __half22float2(*reinterpret_cast<__half2*>(&u2.y));
    float y[4] = { p10.x - lam * p20.x, p10.y - lam * p20.y,
                   p11.x - lam * p21.x, p11.y - lam * p21.y };

    float q = y[0] * y[0] + y[1] * y[1] + y[2] * y[2] + y[3] * y[3];
    q = warp_sum(q);
    float inv = rsqrtf(q * (1.f / 128.f) + 1e-8f);

    __half hv[4];
#pragma unroll
    for (int i = 0; i < 4; i++)
        hv[i] = __float2half((y[i] * inv * w[c + i] + bvec[c + i]) * oml);
    *(uint2*)(out + base) = *(uint2*)hv;
}

// ---------------------------------------------------------------------------
// Launch
// ---------------------------------------------------------------------------
extern "C" void kernel_launch(void* const* d_in, const int* in_sizes, int n_in,
                              void* d_out, int out_size)
{
    const float* x        = (const float*)d_in[0];
    const float* emb      = (const float*)d_in[1];
    const float* l2e_w1   = (const float*)d_in[2];
    const float* l2e_b1   = (const float*)d_in[3];
    const float* l2e_al   = (const float*)d_in[4];
    const float* l2e_be   = (const float*)d_in[5];
    const float* l2e_w2   = (const float*)d_in[6];
    const float* l2e_b2   = (const float*)d_in[7];
    const float* ln1_w    = (const float*)d_in[8];
    const float* ln1_b    = (const float*)d_in[9];
    const float* ln2_w    = (const float*)d_in[10];
    const float* ln2_b    = (const float*)d_in[11];
    const float* qkv_w    = (const float*)d_in[12];
    const float* out_w    = (const float*)d_in[13];
    const float* lq1      = (const float*)d_in[14];
    const float* lk1      = (const float*)d_in[15];
    const float* lq2      = (const float*)d_in[16];
    const float* lk2      = (const float*)d_in[17];
    const float* aln_w    = (const float*)d_in[18];
    const float* aln_b    = (const float*)d_in[19];
    const float* ada_w    = (const float*)d_in[20];
    const float* ada_b    = (const float*)d_in[21];
    const float* ff_w1    = (const float*)d_in[22];
    const float* ff_b1    = (const float*)d_in[23];
    const float* ff_al    = (const float*)d_in[24];
    const float* ff_be    = (const float*)d_in[25];
    const float* ff_w2    = (const float*)d_in[26];
    const float* ff_b2    = (const float*)d_in[27];
    const float* adaf_w   = (const float*)d_in[28];
    const float* adaf_b   = (const float*)d_in[29];
    const float* fin_w    = (const float*)d_in[30];
    const float* fin_b    = (const float*)d_in[31];

    float *h_, *modsall_, *lamv_, *part_;
    __half *th_, *hidh_, *xh_, *qkvh_, *a1h_, *a2h_;
    __half *w_l2e1, *w_l2e2, *w_qkv, *w_out, *w_ff1, *w_ff2, *w_fin;
    cudaGetSymbolAddress((void**)&h_,      g_h);
    cudaGetSymbolAddress((void**)&modsall_,g_modsall);
    cudaGetSymbolAddress((void**)&lamv_,   g_lamv);
    cudaGetSymbolAddress((void**)&part_,   g_part);
    cudaGetSymbolAddress((void**)&th_,     g_th);
    cudaGetSymbolAddress((void**)&hidh_,   g_hidh);
    cudaGetSymbolAddress((void**)&xh_,     g_xh);
    cudaGetSymbolAddress((void**)&qkvh_,   g_qkvh);
    cudaGetSymbolAddress((void**)&a1h_,    g_a1h);
    cudaGetSymbolAddress((void**)&a2h_,    g_a2h);
    cudaGetSymbolAddress((void**)&w_l2e1,  g_w_l2e1);
    cudaGetSymbolAddress((void**)&w_l2e2,  g_w_l2e2);
    cudaGetSymbolAddress((void**)&w_qkv,   g_w_qkv);
    cudaGetSymbolAddress((void**)&w_out,   g_w_out);
    cudaGetSymbolAddress((void**)&w_ff1,   g_w_ff1);
    cudaGetSymbolAddress((void**)&w_ff2,   g_w_ff2);
    cudaGetSymbolAddress((void**)&w_fin,   g_w_fin);

    cudaFuncSetAttribute(flash_h_kernel, cudaFuncAttributeMaxDynamicSharedMemorySize, FT_SMEM);
    cudaFuncSetAttribute(hgemm_kernel<0>, cudaFuncAttributeMaxDynamicSharedMemorySize, HG_SMEM);
    cudaFuncSetAttribute(hgemm_kernel<1>, cudaFuncAttributeMaxDynamicSharedMemorySize, HG_SMEM);
    cudaFuncSetAttribute(hgemm_kernel<2>, cudaFuncAttributeMaxDynamicSharedMemorySize, HG_SMEM);
    cudaFuncSetAttribute(hgemm_kernel<3>, cudaFuncAttributeMaxDynamicSharedMemorySize, HG_SMEM);

    // ---- batched convert ----
    CvtSegs segs;
    const float* ins[8]  = { l2e_w1, l2e_w2, fin_w, qkv_w, out_w, ff_w1, ff_w2, x };
    __half*      outs[8] = { w_l2e1, w_l2e2, w_fin, w_qkv, w_out, w_ff1, w_ff2, xh_ };
    size_t       ns[8]   = { (size_t)64 * EDIM, (size_t)EDIM * EDIM, (size_t)EDIM * 64,
                             (size_t)NB * EDIM * 3 * EDIM, (size_t)NB * EDIM * EDIM,
                             (size_t)NB * EDIM * E4DIM, (size_t)NB * E4DIM * EDIM,
                             (size_t)NTOK * 64 };
    int total4 = 0;
    for (int s = 0; s < 8; s++) {
        segs.in[s]  = (const float4*)ins[s];
        segs.out[s] = (uint2*)outs[s];
        segs.n4[s]  = (int)(ns[s] >> 2);
        total4 += segs.n4[s];
    }
    cvt_all_kernel<<<(total4 + 255) / 256, 256>>>(segs, total4);

    gemm2_part_all<<<dim3(12, 64, 5), 128>>>(emb, ada_w, adaf_w, part_);
    gemm2_reduce_all<<<dim3(12, 1, 5), 256>>>(part_, ada_b, adaf_b, modsall_);
    lambda_all_kernel<<<1, 128>>>(lq1, lk1, lq2, lk2, lamv_);

    auto hgN = [&](const __half* A, const __half* W, const float* bias, float* C,
                   int M, int N, int K) {
        hgemm_kernel<0><<<dim3((N + 127) / 128, M / 128), 256, HG_SMEM>>>(
            A, W, bias, C, M, N, K, nullptr, nullptr, 0);
    };
    auto hgH = [&](const __half* A, const __half* W, const float* bias, __half* C,
                   int M, int N, int K) {
        hgemm_kernel<3><<<dim3((N + 127) / 128, M / 128), 256, HG_SMEM>>>(
            A, W, bias, C, M, N, K, nullptr, nullptr, 0);
    };
    auto hgS = [&](const __half* A, const __half* W, const float* bias, __half* C,
                   int M, int N, int K, const float* al, const float* be) {
        hgemm_kernel<1><<<dim3((N + 127) / 128, M / 128), 256, HG_SMEM>>>(
            A, W, bias, C, M, N, K, al, be, 0);
    };
    auto hgG = [&](const __half* A, const __half* W, float* C,
                   int M, int N, int K, const float* bias, const float* mods, int goff) {
        hgemm_kernel<2><<<dim3((N + 127) / 128, M / 128), 256, HG_SMEM>>>(
            A, W, bias, C, M, N, K, mods, nullptr, goff);
    };

    // latent -> embedding
    hgS(xh_, w_l2e1, l2e_b1, th_, NTOK, EDIM, 64, l2e_al, l2e_be);
    hgN(th_, w_l2e2, l2e_b2, h_, NTOK, EDIM, EDIM);

    for (int i = 0; i < NB; i++) {
        float lam_init = (float)(0.8 - 0.6 * exp(-0.3 * (double)(i + 1)));
        const float* mods_i = modsall_ + (size_t)i * 2 * 6144;

        // attention half
        ln_mod_kernel<true><<<NTOK, 256>>>(h_, ln1_w + i * EDIM, ln1_b + i * EDIM,
                                           mods_i, 6144, 0, 1024, 1e-5f, th_);
        hgH(th_, w_qkv + (size_t)i * EDIM * 3072, nullptr, qkvh_, NTOK, 3072, EDIM);
        flash_h_kernel<<<dim3(16, 16, 2), 128, FT_SMEM>>>(qkvh_, a1h_, a2h_);
        rmsdiff_kernel<<<NTOK, 256>>>(a1h_, a2h_, aln_w + i * 128, aln_b + i * 128,
                                      lamv_ + i, 1.f - lam_init, th_);
        hgG(th_, w_out + (size_t)i * EDIM * EDIM, h_, NTOK, EDIM, EDIM,
            nullptr, mods_i, 4096);

        // MLP half
        ln_mod_kernel<true><<<NTOK, 256>>>(h_, ln2_w + i * EDIM, ln2_b + i * EDIM,
                                           mods_i, 6144, 2048, 3072, 1e-5f, th_);
        hgS(th_, w_ff1 + (size_t)i * EDIM * E4DIM, ff_b1 + i * E4DIM, hidh_,
            NTOK, E4DIM, EDIM, ff_al + i * E4DIM, ff_be + i * E4DIM);
        hgG(hidh_, w_ff2 + (size_t)i * E4DIM * EDIM, h_, NTOK, EDIM, E4DIM,
            ff_b2 + i * EDIM, mods_i, 5120);
    }

    // final adaLN + projection
    ln_mod_kernel<false><<<NTOK, 256>>>(h_, nullptr, nullptr,
                                        modsall_ + (size_t)4 * 2 * 6144, 2048,
                                        0, 1024, 1e-6f, th_);
    hgN(th_, w_fin, fin_b, (float*)d_out, NTOK, 64, EDIM);
}